// round 2
// baseline (speedup 1.0000x reference)
#include <cuda_runtime.h>
#include <cstdint>

// out[b, 0:128]   = emb[idx[b], :]    (128 f32)
// out[b, 128:146] = genre[idx[b], :]  (18 f32)
// B = 1048576, emb = [100000,128] f32, genre = [100000,18] f32
// idx is INT32 (jax downcasts int64 -> int32 without x64 enabled).
//
// One warp per row:
//  - 32 lanes x float4 = 128 floats of embedding (emb row = 512B, 16B aligned)
//  - output row stride 146 f32 = 584 B: 8B-aligned only -> float2 stores (73 per row)
//  - genre row = 18 f32 = 9 float2 (stride 72B, 8B aligned), lanes 0..8

__global__ void __launch_bounds__(256)
item_gather_concat_kernel(const int*    __restrict__ idx,
                          const float4* __restrict__ emb,   // [N, 32] float4
                          const float2* __restrict__ gen,   // [N, 9]  float2
                          float2*       __restrict__ out,   // [B, 73] float2
                          int B)
{
    int gwarp = (int)((blockIdx.x * (unsigned)blockDim.x + threadIdx.x) >> 5);
    int lane  = threadIdx.x & 31;
    if (gwarp >= B) return;

    int item = idx[gwarp];                      // broadcast load (same addr per warp)

    // embedding: one float4 per lane
    float4 e = __ldg(&emb[(size_t)item * 32 + lane]);

    float2* o = out + (size_t)gwarp * 73;
    o[lane * 2 + 0] = make_float2(e.x, e.y);
    o[lane * 2 + 1] = make_float2(e.z, e.w);

    // genre: 9 float2, lanes 0..8
    if (lane < 9) {
        float2 g = __ldg(&gen[(size_t)item * 9 + lane]);
        o[64 + lane] = g;
    }
}

extern "C" void kernel_launch(void* const* d_in, const int* in_sizes, int n_in,
                              void* d_out, int out_size)
{
    const int*    idx = (const int*)   d_in[0];   // item_inputs  int32 [B]
    const float4* emb = (const float4*)d_in[1];   // item_embedding f32 [N,128]
    const float2* gen = (const float2*)d_in[2];   // genre_table    f32 [N,18]
    float2*       out = (float2*)d_out;

    int B = in_sizes[0];                          // 1048576
    int threads = 256;                            // 8 warps/block
    long long total_threads = (long long)B * 32;
    int blocks = (int)((total_threads + threads - 1) / threads);

    item_gather_concat_kernel<<<blocks, threads>>>(idx, emb, gen, out, B);
}

// round 3
// speedup vs baseline: 1.4684x; 1.4684x over previous
#include <cuda_runtime.h>
#include <cstdint>

// out[b, 0:128]   = emb[idx[b], :]    (128 f32)
// out[b, 128:146] = genre[idx[b], :]  (18 f32)
// idx is int32 (JAX downcasts int64 without x64).
//
// Block = 256 threads = 8 warps, handles 32 rows.
// Phase 1: warp w gathers rows 4w..4w+3 (one int4 broadcast -> 4 independent
//          float4 emb gathers + 4 float2x9 genre gathers; MLP ~= 8/warp),
//          staged into smem at the exact output layout (row stride 146 f32).
// Phase 2: block streams its contiguous 32*584 B region to gmem as 1168
//          float4 stores (16B-aligned: 32*584 = 18688 % 16 == 0).

#define ROWS_PER_BLOCK 32
#define SMEM_FLOATS (ROWS_PER_BLOCK * 146)   // 4672 floats = 18688 B
#define CHUNKS (SMEM_FLOATS / 4)             // 1168 float4

__global__ void __launch_bounds__(256)
item_gather_concat_kernel(const int*    __restrict__ idx,
                          const float4* __restrict__ emb,   // [N, 32] float4
                          const float2* __restrict__ gen,   // [N, 9]  float2
                          float4*       __restrict__ out,   // contiguous stream
                          int B)
{
    __shared__ float s[SMEM_FLOATS];

    const int lane    = threadIdx.x & 31;
    const int w       = threadIdx.x >> 5;
    const int rowBase = blockIdx.x * ROWS_PER_BLOCK;

    if (rowBase + ROWS_PER_BLOCK <= B) {
        // ---- Phase 1: gather 4 rows per warp into smem ----
        const int r0 = rowBase + w * 4;
        int4 iv = *(const int4*)(idx + r0);   // broadcast, 16B-aligned
        int items[4] = {iv.x, iv.y, iv.z, iv.w};

        // Issue all independent loads first (MLP), then store.
        float4 e[4];
        float2 g[4];
        #pragma unroll
        for (int j = 0; j < 4; j++)
            e[j] = __ldg(&emb[(size_t)items[j] * 32 + lane]);
        #pragma unroll
        for (int j = 0; j < 4; j++)
            if (lane < 9)
                g[j] = __ldg(&gen[(size_t)items[j] * 9 + lane]);

        #pragma unroll
        for (int j = 0; j < 4; j++) {
            float* srow = s + (w * 4 + j) * 146;
            // 584B row stride is only 8B-aligned -> STS.64 pairs
            *(float2*)(srow + lane * 4)     = make_float2(e[j].x, e[j].y);
            *(float2*)(srow + lane * 4 + 2) = make_float2(e[j].z, e[j].w);
            if (lane < 9)
                *(float2*)(srow + 128 + lane * 2) = g[j];
        }
        __syncthreads();

        // ---- Phase 2: contiguous float4 stream to gmem ----
        const float4* s4 = (const float4*)s;
        float4* o4 = out + (size_t)blockIdx.x * CHUNKS;
        int t = threadIdx.x;
        #pragma unroll
        for (int c = 0; c < 4; c++)
            o4[t + c * 256] = s4[t + c * 256];
        if (t < CHUNKS - 4 * 256)                 // 144 tail chunks
            o4[t + 1024] = s4[t + 1024];
    } else {
        // ---- Tail fallback: per-row float2 path (rare / unused for B=1M) ----
        for (int r = rowBase + w; r < B; r += 8) {
            int item = idx[r];
            float4 e = __ldg(&emb[(size_t)item * 32 + lane]);
            float2* o = (float2*)((float*)out + (size_t)r * 146);
            o[lane * 2 + 0] = make_float2(e.x, e.y);
            o[lane * 2 + 1] = make_float2(e.z, e.w);
            if (lane < 9)
                o[64 + lane] = __ldg(&gen[(size_t)item * 9 + lane]);
        }
    }
}

extern "C" void kernel_launch(void* const* d_in, const int* in_sizes, int n_in,
                              void* d_out, int out_size)
{
    const int*    idx = (const int*)   d_in[0];
    const float4* emb = (const float4*)d_in[1];
    const float2* gen = (const float2*)d_in[2];
    float4*       out = (float4*)d_out;

    int B = in_sizes[0];                                  // 1048576
    int blocks = (B + ROWS_PER_BLOCK - 1) / ROWS_PER_BLOCK;  // 32768

    item_gather_concat_kernel<<<blocks, 256>>>(idx, emb, gen, out, B);
}

// round 4
// speedup vs baseline: 1.5088x; 1.0275x over previous
#include <cuda_runtime.h>
#include <cstdint>

// out[b, 0:128]   = emb[idx[b], :]    (128 f32)
// out[b, 128:146] = genre[idx[b], :]  (18 f32)
// idx is int32 (JAX downcasts int64 without x64).
//
// Block = 256 threads = 8 warps, handles 32 rows.
// Phase 1: warp w gathers rows 4w..4w+3 (one int4 broadcast -> 4 independent
//          float4 emb gathers + genre gathers; MLP ~= 8/warp), staged into
//          smem at the exact output layout (row stride 146 f32).
// Phase 2: block streams its contiguous 32*584 B region to gmem as 1168
//          float4 STREAMING stores (__stcs): evict-first so the 612 MB
//          output stream doesn't evict the 58 MB L2-resident tables.

#define ROWS_PER_BLOCK 32
#define SMEM_FLOATS (ROWS_PER_BLOCK * 146)   // 4672 floats = 18688 B
#define CHUNKS (SMEM_FLOATS / 4)             // 1168 float4

__global__ void __launch_bounds__(256)
item_gather_concat_kernel(const int*    __restrict__ idx,
                          const float4* __restrict__ emb,   // [N, 32] float4
                          const float2* __restrict__ gen,   // [N, 9]  float2
                          float4*       __restrict__ out,   // contiguous stream
                          int B)
{
    __shared__ float s[SMEM_FLOATS];

    const int lane    = threadIdx.x & 31;
    const int w       = threadIdx.x >> 5;
    const int rowBase = blockIdx.x * ROWS_PER_BLOCK;

    if (rowBase + ROWS_PER_BLOCK <= B) {
        // ---- Phase 1: gather 4 rows per warp into smem ----
        const int r0 = rowBase + w * 4;
        int4 iv = __ldcs((const int4*)(idx + r0));   // read-once broadcast
        int items[4] = {iv.x, iv.y, iv.z, iv.w};

        // Issue all independent loads first (MLP), then store.
        float4 e[4];
        float2 g[4];
        #pragma unroll
        for (int j = 0; j < 4; j++)
            e[j] = __ldg(&emb[(size_t)items[j] * 32 + lane]);
        #pragma unroll
        for (int j = 0; j < 4; j++)
            if (lane < 9)
                g[j] = __ldg(&gen[(size_t)items[j] * 9 + lane]);

        #pragma unroll
        for (int j = 0; j < 4; j++) {
            float* srow = s + (w * 4 + j) * 146;
            // 584B row stride is only 8B-aligned -> STS.64 pairs
            *(float2*)(srow + lane * 4)     = make_float2(e[j].x, e[j].y);
            *(float2*)(srow + lane * 4 + 2) = make_float2(e[j].z, e[j].w);
            if (lane < 9)
                *(float2*)(srow + 128 + lane * 2) = g[j];
        }
        __syncthreads();

        // ---- Phase 2: contiguous float4 streaming stores to gmem ----
        const float4* s4 = (const float4*)s;
        float4* o4 = out + (size_t)blockIdx.x * CHUNKS;
        int t = threadIdx.x;
        #pragma unroll
        for (int c = 0; c < 4; c++)
            __stcs(&o4[t + c * 256], s4[t + c * 256]);
        if (t < CHUNKS - 4 * 256)                 // 144 tail chunks
            __stcs(&o4[t + 1024], s4[t + 1024]);
    } else {
        // ---- Tail fallback: per-row float2 path (rare / unused for B=1M) ----
        for (int r = rowBase + w; r < B; r += 8) {
            int item = idx[r];
            float4 e = __ldg(&emb[(size_t)item * 32 + lane]);
            float2* o = (float2*)((float*)out + (size_t)r * 146);
            o[lane * 2 + 0] = make_float2(e.x, e.y);
            o[lane * 2 + 1] = make_float2(e.z, e.w);
            if (lane < 9)
                o[64 + lane] = __ldg(&gen[(size_t)item * 9 + lane]);
        }
    }
}

extern "C" void kernel_launch(void* const* d_in, const int* in_sizes, int n_in,
                              void* d_out, int out_size)
{
    const int*    idx = (const int*)   d_in[0];
    const float4* emb = (const float4*)d_in[1];
    const float2* gen = (const float2*)d_in[2];
    float4*       out = (float4*)d_out;

    int B = in_sizes[0];                                  // 1048576
    int blocks = (B + ROWS_PER_BLOCK - 1) / ROWS_PER_BLOCK;  // 32768

    item_gather_concat_kernel<<<blocks, 256>>>(idx, emb, gen, out, B);
}

// round 5
// speedup vs baseline: 1.6103x; 1.0673x over previous
#include <cuda_runtime.h>
#include <cstdint>

// out[b, 0:128]   = emb[idx[b], :]    (128 f32)
// out[b, 128:146] = genre[idx[b], :]  (18 f32)
// idx is int32 (JAX downcasts int64 without x64).
//
// Warp handles 4 consecutive rows (one int4 idx broadcast -> 4 independent
// float4 emb gathers + 4 predicated genre gathers in flight; MLP ~= 8).
// Stores go DIRECTLY from registers as streaming float2 (__stcs):
//  - no smem round-trip (L1tex was at 68% with staging), no __syncthreads
//  - warp's 4-row region is 2336 B contiguous; STG.64 fully coalesced
//  - .CS keeps the 612 MB output stream from evicting the L2-resident tables

#define ROWS_PER_WARP 4

__global__ void __launch_bounds__(256)
item_gather_concat_kernel(const int*    __restrict__ idx,
                          const float4* __restrict__ emb,   // [N, 32] float4
                          const float2* __restrict__ gen,   // [N, 9]  float2
                          float2*       __restrict__ out,   // [B, 73] float2
                          int B)
{
    const int lane  = threadIdx.x & 31;
    const int gwarp = (int)((blockIdx.x * (unsigned)blockDim.x + threadIdx.x) >> 5);
    const int r0    = gwarp * ROWS_PER_WARP;

    if (r0 + ROWS_PER_WARP <= B) {
        int4 iv = __ldcs((const int4*)(idx + r0));   // read-once broadcast
        int items[4] = {iv.x, iv.y, iv.z, iv.w};

        // Issue all independent gathers first (MLP), then store.
        float4 e[4];
        float2 g[4];
        #pragma unroll
        for (int j = 0; j < 4; j++)
            e[j] = __ldg(&emb[(size_t)items[j] * 32 + lane]);
        #pragma unroll
        for (int j = 0; j < 4; j++)
            if (lane < 9)
                g[j] = __ldg(&gen[(size_t)items[j] * 9 + lane]);

        #pragma unroll
        for (int j = 0; j < 4; j++) {
            float2* o = out + (size_t)(r0 + j) * 73;   // 8B-aligned rows
            __stcs(&o[lane * 2 + 0], make_float2(e[j].x, e[j].y));
            __stcs(&o[lane * 2 + 1], make_float2(e[j].z, e[j].w));
            if (lane < 9)
                __stcs(&o[64 + lane], g[j]);
        }
    } else {
        // Tail fallback (unused for B = 1M): one row at a time.
        for (int r = r0; r < B && r < r0 + ROWS_PER_WARP; r++) {
            int item = idx[r];
            float4 e = __ldg(&emb[(size_t)item * 32 + lane]);
            float2* o = out + (size_t)r * 73;
            o[lane * 2 + 0] = make_float2(e.x, e.y);
            o[lane * 2 + 1] = make_float2(e.z, e.w);
            if (lane < 9)
                o[64 + lane] = __ldg(&gen[(size_t)item * 9 + lane]);
        }
    }
}

extern "C" void kernel_launch(void* const* d_in, const int* in_sizes, int n_in,
                              void* d_out, int out_size)
{
    const int*    idx = (const int*)   d_in[0];
    const float4* emb = (const float4*)d_in[1];
    const float2* gen = (const float2*)d_in[2];
    float2*       out = (float2*)d_out;

    int B = in_sizes[0];                                   // 1048576
    int rowsPerBlock = 8 * ROWS_PER_WARP;                  // 8 warps/block
    int blocks = (B + rowsPerBlock - 1) / rowsPerBlock;    // 32768

    item_gather_concat_kernel<<<blocks, 256>>>(idx, emb, gen, out, B);
}